// round 2
// baseline (speedup 1.0000x reference)
#include <cuda_runtime.h>
#include <math.h>

// Problem constants
#define BB      64
#define TT      2048
#define NIN     64
#define NH      512
#define NOUT    64
#define FPIT    60
#define TOTIT   (FPIT + TT)

// Decomposition
#define CSIZE   8          // CTAs per cluster (H split: 64 rows each)
#define NCLUST  16         // clusters (batch split: 4 batches each)
#define PBATCH  4          // batches per cluster
#define ROWS    64         // H rows owned per CTA
#define THREADS 256

// Shared memory layout (fp32 words). Padding (+1) chosen so both the
// transposed stores at load time and the strided reads in the hot loop are
// bank-conflict-free.
struct SmemLayout {
    float At[NH][ROWS + 1];       // A^T slice: At[j][i] = W_hh[r0+i][j]*omega[j]^2
    float h4[NH][4];              // full h state for 4 batches, [j][p], 16B rows
    float WihT[NIN][ROWS + 1];    // W_ih^T slice
    float Wl[8][NH];              // W_lin rows owned by this rank (8 outputs)
    float u_s[PBATCH][NIN + 1];   // current-step inputs
    float red[4][ROWS][4];        // j-quarter partial sums
    float b_s[ROWS];              // b_ih + b_hh slice
    float bl_s[8];                // b_lin slice
    float om_s[NH];               // omega
};

#define SMEM_BYTES ((int)sizeof(SmemLayout))

// Cross-CTA h exchange buffer (double buffered), L2-resident (256 KB total).
__device__ float g_H[2][NCLUST][NH][4];

__device__ __forceinline__ unsigned long long pack2(float a) {
    unsigned long long r;
    asm("mov.b64 %0, {%1, %1};" : "=l"(r) : "r"(__float_as_uint(a)));
    return r;
}
__device__ __forceinline__ void ffma2(unsigned long long& acc,
                                      unsigned long long a,
                                      unsigned long long b) {
    asm("fma.rn.f32x2 %0, %1, %2, %0;" : "+l"(acc) : "l"(a), "l"(b));
}

extern __shared__ float smem_raw[];

__global__ void __cluster_dims__(CSIZE, 1, 1) __launch_bounds__(THREADS, 1)
rnn_lyapunov_kernel(const float* __restrict__ u,
                    const float* __restrict__ W_ih,
                    const float* __restrict__ W_hh,
                    const float* __restrict__ b_ih,
                    const float* __restrict__ b_hh,
                    const float* __restrict__ omega,
                    const float* __restrict__ W_lin,
                    const float* __restrict__ b_lin,
                    float* __restrict__ out)
{
    SmemLayout* S = reinterpret_cast<SmemLayout*>(smem_raw);
    const int tid  = threadIdx.x;
    const int cid  = blockIdx.x / CSIZE;   // cluster id -> batch group
    const int rank = blockIdx.x % CSIZE;   // rank in cluster -> row slice
    const int r0   = rank * ROWS;
    const int pb0  = cid * PBATCH;

    // ---- one-time loads ----
    for (int j = tid; j < NH; j += THREADS) S->om_s[j] = omega[j];
    __syncthreads();

    // At[j][i] = W_hh[r0+i][j] * omega[j]^2  (coalesced LDG over j,
    // conflict-free STS thanks to the +1 pad)
    for (int idx = tid; idx < ROWS * NH; idx += THREADS) {
        int i = idx >> 9;            // / 512
        int j = idx & (NH - 1);
        float om = S->om_s[j];
        S->At[j][i] = W_hh[(r0 + i) * NH + j] * om * om;
    }
    for (int idx = tid; idx < ROWS * NIN; idx += THREADS) {
        int i = idx >> 6;
        int k = idx & 63;
        S->WihT[k][i] = W_ih[(r0 + i) * NIN + k];
    }
    for (int idx = tid; idx < 8 * NH; idx += THREADS) {
        int o = idx >> 9;
        int j = idx & (NH - 1);
        S->Wl[o][j] = W_lin[(rank * 8 + o) * NH + j];
    }
    if (tid < ROWS) S->b_s[tid] = b_ih[r0 + tid] + b_hh[r0 + tid];
    if (tid < 8)    S->bl_s[tid] = b_lin[rank * 8 + tid];
    for (int idx = tid; idx < NH * 4; idx += THREADS)
        (reinterpret_cast<float*>(S->h4))[idx] = 0.0f;  // h starts at zero
    __syncthreads();

    // thread mappings
    const int i_mv = tid & 63;    // matvec: row
    const int jh   = tid >> 6;    // matvec: j-quarter (also batch idx for u load)
    const int i2   = tid >> 2;    // reduce/tanh: row
    const int p2   = tid & 3;     // reduce/tanh: batch
    const int pair = tid >> 3;    // head: (out, batch) pair
    const int seg  = tid & 7;     // head: j segment
    const int oo   = pair >> 2;   // head: local output col (0..7)
    const int pp   = pair & 3;    // head: batch

    for (int kk = 0; kk < TOTIT; ++kk) {
        const int t  = kk - FPIT;
        const int tu = (t < 0) ? 0 : t;

        // Input for this step (consumed after the syncthreads; LDG latency
        // hides under the matvec). jh doubles as the batch index here.
        const float u_reg = u[(pb0 + jh) * (TT * NIN) + tu * NIN + i_mv];

        // ---- matvec: acc[p] = sum_j At[j][i] * h[j][p], j-quarter per thread
        unsigned long long acc01 = 0ull, acc23 = 0ull;
        {
            const float* Atp = &S->At[jh * 128][0];
            const ulonglong2* h4p =
                reinterpret_cast<const ulonglong2*>(&S->h4[jh * 128][0]);
            #pragma unroll 8
            for (int jj = 0; jj < 128; ++jj) {
                float a = Atp[jj * (ROWS + 1) + i_mv];   // conflict-free LDS
                ulonglong2 hv = h4p[jj];                 // broadcast LDS.128
                unsigned long long aa = pack2(a);
                ffma2(acc01, aa, hv.x);
                ffma2(acc23, aa, hv.y);
            }
        }
        *reinterpret_cast<ulonglong2*>(&S->red[jh][i_mv][0]) =
            make_ulonglong2(acc01, acc23);
        S->u_s[jh][i_mv] = u_reg;
        __syncthreads();

        // ---- reduce partials + input projection + tanh, write own slice ----
        {
            float s = S->b_s[i2];
            s += S->red[0][i2][p2] + S->red[1][i2][p2] +
                 S->red[2][i2][p2] + S->red[3][i2][p2];
            #pragma unroll 8
            for (int k = 0; k < NIN; ++k)
                s = fmaf(S->u_s[p2][k], S->WihT[k][i2], s);
            float hn = tanhf(s);
            float* Hg = &g_H[kk & 1][cid][0][0];
            __stcg(&Hg[(r0 + i2) * 4 + p2], hn);   // coalesced: addr == tid
        }

        // cluster barrier: orders the L2 writes above vs. reads below
        asm volatile("barrier.cluster.arrive.aligned;" ::: "memory");
        asm volatile("barrier.cluster.wait.aligned;"   ::: "memory");

        // ---- gather full h (all 8 slices) back into SMEM ----
        {
            const float4* Hg4 =
                reinterpret_cast<const float4*>(&g_H[kk & 1][cid][0][0]);
            float4 v0 = __ldcg(Hg4 + tid);
            float4 v1 = __ldcg(Hg4 + tid + THREADS);
            reinterpret_cast<float4*>(S->h4)[tid]           = v0;
            reinterpret_cast<float4*>(S->h4)[tid + THREADS] = v1;
        }
        __syncthreads();

        // ---- fused linear head: this rank owns 8 output columns ----
        if (t >= 0) {
            float acc = 0.0f;
            const float* wl  = &S->Wl[oo][0];
            const float* h4f = reinterpret_cast<const float*>(S->h4);
            #pragma unroll 8
            for (int jj = 0; jj < 64; ++jj) {
                int j = jj * 8 + seg;
                acc = fmaf(wl[j], h4f[j * 4 + pp], acc);
            }
            acc += __shfl_xor_sync(0xffffffffu, acc, 1);
            acc += __shfl_xor_sync(0xffffffffu, acc, 2);
            acc += __shfl_xor_sync(0xffffffffu, acc, 4);
            if (seg == 0)
                out[(pb0 + pp) * (TT * NOUT) + t * NOUT + rank * 8 + oo] =
                    acc + S->bl_s[oo];
        }
    }
}

extern "C" void kernel_launch(void* const* d_in, const int* in_sizes, int n_in,
                              void* d_out, int out_size)
{
    const float* u     = (const float*)d_in[0];
    const float* W_ih  = (const float*)d_in[1];
    const float* W_hh  = (const float*)d_in[2];
    const float* b_ih  = (const float*)d_in[3];
    const float* b_hh  = (const float*)d_in[4];
    const float* omega = (const float*)d_in[5];
    const float* W_lin = (const float*)d_in[6];
    const float* b_lin = (const float*)d_in[7];
    float* out = (float*)d_out;

    cudaFuncSetAttribute(rnn_lyapunov_kernel,
                         cudaFuncAttributeMaxDynamicSharedMemorySize,
                         SMEM_BYTES);

    rnn_lyapunov_kernel<<<NCLUST * CSIZE, THREADS, SMEM_BYTES>>>(
        u, W_ih, W_hh, b_ih, b_hh, omega, W_lin, b_lin, out);
}

// round 3
// speedup vs baseline: 1.4454x; 1.4454x over previous
#include <cuda_runtime.h>
#include <cstdint>

// Problem constants
#define BB      64
#define TT      2048
#define NIN     64
#define NH      512
#define NOUT    64
#define FPIT    60
#define TOTIT   (FPIT + TT)

// Decomposition
#define CSIZE   8            // CTAs per cluster (H split: 64 rows each)
#define NCLUST  16           // clusters (batch split: 4 batches each)
#define PBATCH  4
#define ROWS    64           // H rows owned per CTA
#define THREADS 256
#define JEXT    (NH + NIN)   // 576: recurrent + input-projection rows
#define JW      (JEXT / 8)   // 72 j per warp

struct Smem {
    float Aext[JEXT][ROWS];   // [j][i]: j<512 -> W_hh^T*omega^2, j>=512 -> W_ih^T
    float hx[2][JEXT][4];     // extended state [j][batch], double buffered
    float red[8][ROWS][4];    // per-warp partials
    float Wl[8][NH];          // this rank's 8 W_lin rows
    float bs[ROWS];           // b_ih + b_hh slice
    float bl[8];              // b_lin slice
    float om[NH];             // omega
};
#define SMEM_BYTES ((int)sizeof(Smem))
#define HXBUF_BYTES (JEXT * 4 * 4)   // 9216 bytes per hx buffer

__device__ __forceinline__ uint32_t smem_u32(const void* p) {
    uint32_t a;
    asm("{ .reg .u64 t; cvta.to.shared.u64 t, %1; cvt.u32.u64 %0, t; }"
        : "=r"(a) : "l"(p));
    return a;
}
__device__ __forceinline__ unsigned long long pack2(float a) {
    unsigned long long r;
    asm("mov.b64 %0, {%1, %1};" : "=l"(r) : "r"(__float_as_uint(a)));
    return r;
}
__device__ __forceinline__ unsigned long long packab(float a, float b) {
    unsigned long long r;
    asm("mov.b64 %0, {%1, %2};" : "=l"(r) : "r"(__float_as_uint(a)), "r"(__float_as_uint(b)));
    return r;
}
__device__ __forceinline__ void unpack2(unsigned long long v, float& a, float& b) {
    uint32_t x, y;
    asm("mov.b64 {%0, %1}, %2;" : "=r"(x), "=r"(y) : "l"(v));
    a = __uint_as_float(x); b = __uint_as_float(y);
}
__device__ __forceinline__ void ffma2(unsigned long long& acc,
                                      unsigned long long a,
                                      unsigned long long b) {
    asm("fma.rn.f32x2 %0, %1, %2, %0;" : "+l"(acc) : "l"(a), "l"(b));
}
__device__ __forceinline__ float tanh_fast(float x) {
    float r;
    asm("tanh.approx.f32 %0, %1;" : "=f"(r) : "f"(x));
    return r;
}

// Fused linear head for one timestep: warp wid owns output column rank*8+wid,
// lanes cover j strided (j = k*32 + lane) -> conflict-free LDS.128 of hx rows.
__device__ __forceinline__ void do_head(const Smem* S, int buf, int wid, int lane,
                                        int pb0, int rank, int tt,
                                        float* __restrict__ out)
{
    unsigned long long a01 = 0ull, a23 = 0ull;
    const float* wl = &S->Wl[wid][0];
    const ulonglong2* hp = reinterpret_cast<const ulonglong2*>(&S->hx[buf][0][0]);
    #pragma unroll
    for (int k = 0; k < 16; ++k) {
        int j = k * 32 + lane;
        float w = wl[j];
        ulonglong2 hv = hp[j];
        unsigned long long ww = pack2(w);
        ffma2(a01, ww, hv.x);
        ffma2(a23, ww, hv.y);
    }
    float s0, s1, s2, s3;
    unpack2(a01, s0, s1);
    unpack2(a23, s2, s3);
    #pragma unroll
    for (int m = 16; m >= 1; m >>= 1) {
        s0 += __shfl_xor_sync(0xffffffffu, s0, m);
        s1 += __shfl_xor_sync(0xffffffffu, s1, m);
        s2 += __shfl_xor_sync(0xffffffffu, s2, m);
        s3 += __shfl_xor_sync(0xffffffffu, s3, m);
    }
    if (lane < 4) {
        float v = (lane & 1) ? ((lane & 2) ? s3 : s1)
                             : ((lane & 2) ? s2 : s0);
        out[(pb0 + lane) * (TT * NOUT) + tt * NOUT + rank * 8 + wid] =
            v + S->bl[wid];
    }
}

extern __shared__ float smem_raw[];

__global__ void __cluster_dims__(CSIZE, 1, 1) __launch_bounds__(THREADS, 1)
rnn_lyapunov_kernel(const float* __restrict__ u,
                    const float* __restrict__ W_ih,
                    const float* __restrict__ W_hh,
                    const float* __restrict__ b_ih,
                    const float* __restrict__ b_hh,
                    const float* __restrict__ omega,
                    const float* __restrict__ W_lin,
                    const float* __restrict__ b_lin,
                    float* __restrict__ out)
{
    Smem* S = reinterpret_cast<Smem*>(smem_raw);
    const int tid  = threadIdx.x;
    const int wid  = tid >> 5;
    const int lane = tid & 31;

    uint32_t rank;
    asm("mov.u32 %0, %%cluster_ctarank;" : "=r"(rank));
    const int cid = blockIdx.x >> 3;       // cluster id -> batch group
    const int r0  = (int)rank * ROWS;
    const int pb0 = cid * PBATCH;

    // ---- one-time loads ----
    for (int j = tid; j < NH; j += THREADS) S->om[j] = omega[j];
    __syncthreads();

    for (int idx = tid; idx < ROWS * NH; idx += THREADS) {
        int i = idx >> 9;
        int j = idx & (NH - 1);
        float om = S->om[j];
        S->Aext[j][i] = W_hh[(r0 + i) * NH + j] * om * om;
    }
    for (int idx = tid; idx < ROWS * NIN; idx += THREADS) {
        int i = idx >> 6;
        int k = idx & 63;
        S->Aext[NH + k][i] = W_ih[(r0 + i) * NIN + k];
    }
    for (int idx = tid; idx < 8 * NH; idx += THREADS) {
        int o = idx >> 9;
        int j = idx & (NH - 1);
        S->Wl[o][j] = W_lin[((int)rank * 8 + o) * NH + j];
    }
    if (tid < ROWS) S->bs[tid] = b_ih[r0 + tid] + b_hh[r0 + tid];
    if (tid < 8)    S->bl[tid] = b_lin[(int)rank * 8 + tid];

    // hx[0]: h part zero, u part = u[:,0,:]
    for (int idx = tid; idx < NH * 4; idx += THREADS)
        (&S->hx[0][0][0])[idx] = 0.0f;
    {
        int p = tid >> 6, k = tid & 63;
        S->hx[0][NH + k][p] = u[(pb0 + p) * (TT * NIN) + 0 * NIN + k];
    }
    __syncthreads();

    // mappings
    const int i2 = tid >> 2;   // reduce/exchange: row
    const int p2 = tid & 3;    // reduce/exchange: batch
    const int pk = tid >> 6;   // u prefetch: batch
    const int ku = tid & 63;   // u prefetch: input idx
    const int jbase = wid * JW;

    // precomputed DSMEM destinations for my row (all 8 ranks, 2 per thread)
    uint32_t myrow = smem_u32(&S->hx[0][r0 + i2][0]);
    uint32_t dstA, dstB;
    asm("mapa.shared::cluster.u32 %0, %1, %2;" : "=r"(dstA) : "r"(myrow), "r"((uint32_t)(p2 * 2)));
    asm("mapa.shared::cluster.u32 %0, %1, %2;" : "=r"(dstB) : "r"(myrow), "r"((uint32_t)(p2 * 2 + 1)));

    const float2* Abase = reinterpret_cast<const float2*>(&S->Aext[jbase][0]);

    for (int kk = 0; kk < TOTIT; ++kk) {
        const int cur = kk & 1;
        const int nxt = cur ^ 1;
        const int t   = kk - FPIT;

        // prefetch u for step kk+1 (clamped; hidden under the matvec)
        int tn = kk + 1 - FPIT;
        tn = (tn < 0) ? 0 : ((tn > TT - 1) ? (TT - 1) : tn);
        const float u_next = u[(pb0 + pk) * (TT * NIN) + tn * NIN + ku];

        // ---- extended matvec: rows = 2 per lane, j-eighth per warp ----
        unsigned long long r0b01 = 0ull, r0b23 = 0ull, r1b01 = 0ull, r1b23 = 0ull;
        {
            const float2* Ap = Abase + lane;                       // A[j][2*lane]
            const ulonglong2* hp =
                reinterpret_cast<const ulonglong2*>(&S->hx[cur][jbase][0]);
            #pragma unroll 8
            for (int jj = 0; jj < JW; ++jj) {
                float2 a = Ap[jj * 32];
                ulonglong2 hv = hp[jj];
                unsigned long long a0 = pack2(a.x);
                unsigned long long a1 = pack2(a.y);
                ffma2(r0b01, a0, hv.x);
                ffma2(r0b23, a0, hv.y);
                ffma2(r1b01, a1, hv.x);
                ffma2(r1b23, a1, hv.y);
            }
        }
        {
            ulonglong2* rp = reinterpret_cast<ulonglong2*>(&S->red[wid][2 * lane][0]);
            rp[0] = make_ulonglong2(r0b01, r0b23);
            rp[1] = make_ulonglong2(r1b01, r1b23);
        }
        __syncthreads();

        // ---- reduce 8 partials + bias, tanh ----
        float s = S->bs[i2];
        #pragma unroll
        for (int q = 0; q < 8; ++q) s += S->red[q][i2][p2];
        const float hn = tanh_fast(s);

        // ---- quad transpose -> float4 of (h0..h3) in every lane ----
        float a = hn;
        float b = __shfl_xor_sync(0xffffffffu, a, 1);
        float v0 = (p2 & 1) ? b : a;
        float v1 = (p2 & 1) ? a : b;
        float c0 = __shfl_xor_sync(0xffffffffu, v0, 2);
        float c1 = __shfl_xor_sync(0xffffffffu, v1, 2);
        float h0, h1, h2, h3;
        if (p2 < 2) { h0 = v0; h1 = v1; h2 = c0; h3 = c1; }
        else        { h0 = c0; h1 = c1; h2 = v0; h3 = v1; }
        unsigned long long lo = packab(h0, h1);
        unsigned long long hi = packab(h2, h3);

        // ---- DSMEM push of my rows into all 8 CTAs' hx[nxt] ----
        const uint32_t off = (uint32_t)nxt * HXBUF_BYTES;
        asm volatile("st.shared::cluster.b64 [%0], %1;" :: "r"(dstA + off),     "l"(lo) : "memory");
        asm volatile("st.shared::cluster.b64 [%0], %1;" :: "r"(dstA + off + 8), "l"(hi) : "memory");
        asm volatile("st.shared::cluster.b64 [%0], %1;" :: "r"(dstB + off),     "l"(lo) : "memory");
        asm volatile("st.shared::cluster.b64 [%0], %1;" :: "r"(dstB + off + 8), "l"(hi) : "memory");

        // local store of next step's input rows
        S->hx[nxt][NH + ku][pk] = u_next;

        // release my writes, then hide the head under the cluster wait
        asm volatile("barrier.cluster.arrive.aligned;" ::: "memory");

        if (t >= 1)
            do_head(S, cur, wid, lane, pb0, (int)rank, t - 1, out);

        asm volatile("barrier.cluster.wait.aligned;" ::: "memory");
    }

    // final head: h_{TT-1} lives in hx[TOTIT&1]
    do_head(S, TOTIT & 1, wid, lane, pb0, (int)rank, TT - 1, out);
}

extern "C" void kernel_launch(void* const* d_in, const int* in_sizes, int n_in,
                              void* d_out, int out_size)
{
    const float* u     = (const float*)d_in[0];
    const float* W_ih  = (const float*)d_in[1];
    const float* W_hh  = (const float*)d_in[2];
    const float* b_ih  = (const float*)d_in[3];
    const float* b_hh  = (const float*)d_in[4];
    const float* omega = (const float*)d_in[5];
    const float* W_lin = (const float*)d_in[6];
    const float* b_lin = (const float*)d_in[7];
    float* out = (float*)d_out;

    cudaFuncSetAttribute(rnn_lyapunov_kernel,
                         cudaFuncAttributeMaxDynamicSharedMemorySize,
                         SMEM_BYTES);

    rnn_lyapunov_kernel<<<NCLUST * CSIZE, THREADS, SMEM_BYTES>>>(
        u, W_ih, W_hh, b_ih, b_hh, omega, W_lin, b_lin, out);
}

// round 4
// speedup vs baseline: 1.4738x; 1.0197x over previous
#include <cuda_runtime.h>
#include <cstdint>

// Problem constants
#define BB      64
#define TT      2048
#define NIN     64
#define NH      512
#define NOUT    64
#define FPIT    60
#define TOTIT   (FPIT + TT)

// Decomposition
#define CSIZE   8            // CTAs per cluster (H split: 64 rows each)
#define NCLUST  16           // clusters (batch split: 4 batches each)
#define PBATCH  4
#define ROWS    64           // H rows owned per CTA
#define THREADS 512
#define NWARP   16
#define JEXT    (NH + NIN)   // 576
#define JW      (JEXT / NWARP) // 36 j per warp

struct Smem {
    float Aext[JEXT][ROWS];     // [j][i]
    float hx[2][JEXT][4];       // extended state, double buffered
    float red[NWARP][ROWS][4];  // per-warp partials
    float Wl[8][NH];            // this rank's 8 W_lin rows
    float bs[ROWS];
    float bl[8];
    float om[NH];
    unsigned long long full[2]; // mbarriers (count=8), one per hx buffer
};
#define SMEM_BYTES  ((int)sizeof(Smem))
#define HXBUF_BYTES (JEXT * 4 * 4)   // 9216

__device__ __forceinline__ uint32_t smem_u32(const void* p) {
    uint32_t a;
    asm("{ .reg .u64 t; cvta.to.shared.u64 t, %1; cvt.u32.u64 %0, t; }"
        : "=r"(a) : "l"(p));
    return a;
}
__device__ __forceinline__ uint32_t mapa_u32(uint32_t addr, uint32_t rank) {
    uint32_t r;
    asm("mapa.shared::cluster.u32 %0, %1, %2;" : "=r"(r) : "r"(addr), "r"(rank));
    return r;
}
__device__ __forceinline__ unsigned long long pack2(float a) {
    unsigned long long r;
    asm("mov.b64 %0, {%1, %1};" : "=l"(r) : "r"(__float_as_uint(a)));
    return r;
}
__device__ __forceinline__ unsigned long long packab(float a, float b) {
    unsigned long long r;
    asm("mov.b64 %0, {%1, %2};" : "=l"(r) : "r"(__float_as_uint(a)), "r"(__float_as_uint(b)));
    return r;
}
__device__ __forceinline__ void unpack2(unsigned long long v, float& a, float& b) {
    uint32_t x, y;
    asm("mov.b64 {%0, %1}, %2;" : "=r"(x), "=r"(y) : "l"(v));
    a = __uint_as_float(x); b = __uint_as_float(y);
}
__device__ __forceinline__ void ffma2(unsigned long long& acc,
                                      unsigned long long a,
                                      unsigned long long b) {
    asm("fma.rn.f32x2 %0, %1, %2, %0;" : "+l"(acc) : "l"(a), "l"(b));
}
__device__ __forceinline__ float tanh_fast(float x) {
    float r;
    asm("tanh.approx.f32 %0, %1;" : "=f"(r) : "f"(x));
    return r;
}

#define MBARRIER_INIT(addr, cnt) \
    asm volatile("mbarrier.init.shared.b64 [%0], %1;" :: "r"(addr), "r"(cnt) : "memory")

// remote arrive with cluster-scope release (orders our prior DSMEM stores)
#define MBAR_ARRIVE_REMOTE(addr) \
    asm volatile("mbarrier.arrive.release.cluster.shared::cluster.b64 _, [%0];" \
                 :: "r"(addr) : "memory")

// local parity wait with cluster-scope acquire
#define MBAR_WAIT_CLUSTER(mbar, parity) do {                                     \
    uint32_t _m = (mbar), _p = (parity);                                         \
    asm volatile(                                                                \
        "{\n\t.reg .pred P1;\n\t"                                                \
        "WL_%=:\n\t"                                                             \
        "mbarrier.try_wait.parity.acquire.cluster.shared::cta.b64 P1, [%0], %1, 0x989680;\n\t" \
        "@P1 bra.uni WD_%=;\n\t"                                                 \
        "bra.uni WL_%=;\n\t"                                                     \
        "WD_%=:\n\t}"                                                            \
        :: "r"(_m), "r"(_p) : "memory");                                         \
} while (0)

// Fused linear head: warp wid (<8) owns output column rank*8+wid.
__device__ __forceinline__ void do_head(const Smem* S, int buf, int wid, int lane,
                                        int pb0, int rank, int tt,
                                        float* __restrict__ out)
{
    unsigned long long a01 = 0ull, a23 = 0ull;
    const float* wl = &S->Wl[wid][0];
    const ulonglong2* hp = reinterpret_cast<const ulonglong2*>(&S->hx[buf][0][0]);
    #pragma unroll
    for (int k = 0; k < 16; ++k) {
        int j = k * 32 + lane;
        float w = wl[j];
        ulonglong2 hv = hp[j];
        unsigned long long ww = pack2(w);
        ffma2(a01, ww, hv.x);
        ffma2(a23, ww, hv.y);
    }
    float s0, s1, s2, s3;
    unpack2(a01, s0, s1);
    unpack2(a23, s2, s3);
    #pragma unroll
    for (int m = 16; m >= 1; m >>= 1) {
        s0 += __shfl_xor_sync(0xffffffffu, s0, m);
        s1 += __shfl_xor_sync(0xffffffffu, s1, m);
        s2 += __shfl_xor_sync(0xffffffffu, s2, m);
        s3 += __shfl_xor_sync(0xffffffffu, s3, m);
    }
    if (lane < 4) {
        float v = (lane & 1) ? ((lane & 2) ? s3 : s1)
                             : ((lane & 2) ? s2 : s0);
        out[(pb0 + lane) * (TT * NOUT) + tt * NOUT + rank * 8 + wid] =
            v + S->bl[wid];
    }
}

extern __shared__ float smem_raw[];

__global__ void __cluster_dims__(CSIZE, 1, 1) __launch_bounds__(THREADS, 1)
rnn_lyapunov_kernel(const float* __restrict__ u,
                    const float* __restrict__ W_ih,
                    const float* __restrict__ W_hh,
                    const float* __restrict__ b_ih,
                    const float* __restrict__ b_hh,
                    const float* __restrict__ omega,
                    const float* __restrict__ W_lin,
                    const float* __restrict__ b_lin,
                    float* __restrict__ out)
{
    Smem* S = reinterpret_cast<Smem*>(smem_raw);
    const int tid  = threadIdx.x;
    const int wid  = tid >> 5;
    const int lane = tid & 31;

    uint32_t rank;
    asm("mov.u32 %0, %%cluster_ctarank;" : "=r"(rank));
    const int cid = blockIdx.x >> 3;
    const int r0  = (int)rank * ROWS;
    const int pb0 = cid * PBATCH;

    // ---- one-time loads ----
    for (int j = tid; j < NH; j += THREADS) S->om[j] = omega[j];
    __syncthreads();

    for (int idx = tid; idx < ROWS * NH; idx += THREADS) {
        int i = idx >> 9;
        int j = idx & (NH - 1);
        float om = S->om[j];
        S->Aext[j][i] = W_hh[(r0 + i) * NH + j] * om * om;
    }
    for (int idx = tid; idx < ROWS * NIN; idx += THREADS) {
        int i = idx >> 6;
        int k = idx & 63;
        S->Aext[NH + k][i] = W_ih[(r0 + i) * NIN + k];
    }
    for (int idx = tid; idx < 8 * NH; idx += THREADS) {
        int o = idx >> 9;
        int j = idx & (NH - 1);
        S->Wl[o][j] = W_lin[((int)rank * 8 + o) * NH + j];
    }
    if (tid < ROWS) S->bs[tid] = b_ih[r0 + tid] + b_hh[r0 + tid];
    if (tid < 8)    S->bl[tid] = b_lin[(int)rank * 8 + tid];

    // hx[0]: h part zero, u part = u[:,0,:]
    for (int idx = tid; idx < NH * 4; idx += THREADS)
        (&S->hx[0][0][0])[idx] = 0.0f;
    if (tid < 256) {
        int p = tid >> 6, k = tid & 63;
        S->hx[0][NH + k][p] = u[(pb0 + p) * (TT * NIN) + 0 * NIN + k];
    }
    if (tid == 0) {
        MBARRIER_INIT(smem_u32(&S->full[0]), 8);
        MBARRIER_INIT(smem_u32(&S->full[1]), 8);
    }
    __syncthreads();
    // all CTAs' SMEM + mbarriers ready before any remote traffic
    asm volatile("barrier.cluster.arrive.aligned;" ::: "memory");
    asm volatile("barrier.cluster.wait.aligned;"   ::: "memory");

    // mappings (epilogue threads = tid<256)
    const int i2 = tid >> 2;
    const int p2 = tid & 3;
    const int pk = tid >> 6;
    const int ku = tid & 63;
    const int jbase = wid * JW;

    // DSMEM destinations for my (i2,p2) row: ranks p2*2 and p2*2+1
    uint32_t dstA = 0, dstB = 0;
    if (tid < 256) {
        uint32_t myrow = smem_u32(&S->hx[0][r0 + i2][0]);
        dstA = mapa_u32(myrow, (uint32_t)(p2 * 2));
        dstB = mapa_u32(myrow, (uint32_t)(p2 * 2 + 1));
    }
    // remote full-barrier addresses (warp 8, lanes 0-7)
    uint32_t ra0 = 0, ra1 = 0;
    const uint32_t fl0 = smem_u32(&S->full[0]);
    const uint32_t fl1 = smem_u32(&S->full[1]);
    if (wid == 8 && lane < 8) {
        ra0 = mapa_u32(fl0, (uint32_t)lane);
        ra1 = mapa_u32(fl1, (uint32_t)lane);
    }

    const float2* Abase = reinterpret_cast<const float2*>(&S->Aext[jbase][0]);

    for (int kk = 0; kk < TOTIT; ++kk) {
        const int cur = kk & 1;
        const int nxt = cur ^ 1;
        const int t   = kk - FPIT;

        // prefetch u for step kk+1 (clamped; hidden under the matvec)
        float u_next = 0.0f;
        if (tid < 256) {
            int tn = kk + 1 - FPIT;
            tn = (tn < 0) ? 0 : ((tn > TT - 1) ? (TT - 1) : tn);
            u_next = u[(pb0 + pk) * (TT * NIN) + tn * NIN + ku];
        }

        // ---- extended matvec: 2 rows per lane, 36 j per warp ----
        unsigned long long r0b01 = 0ull, r0b23 = 0ull, r1b01 = 0ull, r1b23 = 0ull;
        {
            const float2* Ap = Abase + lane;
            const ulonglong2* hp =
                reinterpret_cast<const ulonglong2*>(&S->hx[cur][jbase][0]);
            #pragma unroll 12
            for (int jj = 0; jj < JW; ++jj) {
                float2 a = Ap[jj * 32];
                ulonglong2 hv = hp[jj];
                unsigned long long a0 = pack2(a.x);
                unsigned long long a1 = pack2(a.y);
                ffma2(r0b01, a0, hv.x);
                ffma2(r0b23, a0, hv.y);
                ffma2(r1b01, a1, hv.x);
                ffma2(r1b23, a1, hv.y);
            }
        }
        {
            ulonglong2* rp = reinterpret_cast<ulonglong2*>(&S->red[wid][2 * lane][0]);
            rp[0] = make_ulonglong2(r0b01, r0b23);
            rp[1] = make_ulonglong2(r1b01, r1b23);
        }
        __syncthreads();

        // ---- reduce 16 partials + bias, tanh, transpose, DSMEM push ----
        if (tid < 256) {
            float s = S->bs[i2];
            const float* rp = &S->red[0][i2][p2];
            #pragma unroll
            for (int q = 0; q < NWARP; ++q) s += rp[q * ROWS * 4];
            const float hn = tanh_fast(s);

            // quad transpose -> (h0..h3) packed in every lane
            float a = hn;
            float b = __shfl_xor_sync(0xffffffffu, a, 1);
            float v0 = (p2 & 1) ? b : a;
            float v1 = (p2 & 1) ? a : b;
            float c0 = __shfl_xor_sync(0xffffffffu, v0, 2);
            float c1 = __shfl_xor_sync(0xffffffffu, v1, 2);
            float h0, h1, h2, h3;
            if (p2 < 2) { h0 = v0; h1 = v1; h2 = c0; h3 = c1; }
            else        { h0 = c0; h1 = c1; h2 = v0; h3 = v1; }
            unsigned long long lo = packab(h0, h1);
            unsigned long long hi = packab(h2, h3);

            const uint32_t off = (uint32_t)nxt * HXBUF_BYTES;
            asm volatile("st.shared::cluster.b64 [%0], %1;" :: "r"(dstA + off),     "l"(lo) : "memory");
            asm volatile("st.shared::cluster.b64 [%0], %1;" :: "r"(dstA + off + 8), "l"(hi) : "memory");
            asm volatile("st.shared::cluster.b64 [%0], %1;" :: "r"(dstB + off),     "l"(lo) : "memory");
            asm volatile("st.shared::cluster.b64 [%0], %1;" :: "r"(dstB + off + 8), "l"(hi) : "memory");

            // local store of next step's input rows
            S->hx[nxt][NH + ku][pk] = u_next;
        }
        __syncthreads();

        // warp 8: release-arrive on every CTA's full[nxt]
        if (wid == 8 && lane < 8) {
            uint32_t ra = nxt ? ra1 : ra0;
            MBAR_ARRIVE_REMOTE(ra);
        }

        // head for step t-1 overlapped with the wait window
        if (wid < 8 && t >= 1)
            do_head(S, cur, wid, lane, pb0, (int)rank, t - 1, out);

        // wait for all 8 slices of hx[nxt]
        MBAR_WAIT_CLUSTER(nxt ? fl1 : fl0, (uint32_t)((kk >> 1) & 1));
    }

    // final head: h_{TT-1} lives in hx[TOTIT&1]
    if (wid < 8)
        do_head(S, TOTIT & 1, wid, lane, pb0, (int)rank, TT - 1, out);
}

extern "C" void kernel_launch(void* const* d_in, const int* in_sizes, int n_in,
                              void* d_out, int out_size)
{
    const float* u     = (const float*)d_in[0];
    const float* W_ih  = (const float*)d_in[1];
    const float* W_hh  = (const float*)d_in[2];
    const float* b_ih  = (const float*)d_in[3];
    const float* b_hh  = (const float*)d_in[4];
    const float* omega = (const float*)d_in[5];
    const float* W_lin = (const float*)d_in[6];
    const float* b_lin = (const float*)d_in[7];
    float* out = (float*)d_out;

    cudaFuncSetAttribute(rnn_lyapunov_kernel,
                         cudaFuncAttributeMaxDynamicSharedMemorySize,
                         SMEM_BYTES);

    rnn_lyapunov_kernel<<<NCLUST * CSIZE, THREADS, SMEM_BYTES>>>(
        u, W_ih, W_hh, b_ih, b_hh, omega, W_lin, b_lin, out);
}